// round 9
// baseline (speedup 1.0000x reference)
#include <cuda_runtime.h>
#include <math.h>

#define N_NODES  50000
#define N_GRAPHS 500
#define N_EDGES  800000
#define D        128
#define HG_LD    (3 * D)   // 384

#define SCAN_BLK 256
#define N_SCAN_BLKS ((N_NODES + SCAN_BLK - 1) / SCAN_BLK)   // 196

// ---------------- scratch (no allocs) ----------------
__device__ float g_h[N_NODES * D];          // ping buffer
__device__ float g_h2[N_NODES * D];         // pong buffer (fused kernel reads X and writes H concurrently)
__device__ float g_out_inv[N_NODES];
__device__ float g_in_inv[N_NODES];
__device__ int   g_deg_out[N_NODES];
__device__ int   g_deg_in[N_NODES];
__device__ int   g_off[N_NODES + 1];        // CSR offsets by dst
__device__ int   g_cursor[N_NODES];         // fill cursors
__device__ int   g_blk_off[N_SCAN_BLKS + 1];
__device__ int2  g_edges[N_EDGES];          // {src, out_inv[src] bits}

// ---------------- packed f32x2 helpers ----------------
__device__ __forceinline__ void ffma2(unsigned long long& acc,
                                      unsigned long long x,
                                      unsigned long long w) {
    asm("fma.rn.f32x2 %0, %1, %2, %0;" : "+l"(acc) : "l"(x), "l"(w));
}
__device__ __forceinline__ unsigned long long bc2(float x) {
    unsigned long long r;
    asm("mov.b64 %0, {%1, %1};" : "=l"(r) : "f"(x));
    return r;
}
__device__ __forceinline__ float2 unpk2(unsigned long long v) {
    float2 r;
    asm("mov.b64 {%0, %1}, %2;" : "=f"(r.x), "=f"(r.y) : "l"(v));
    return r;
}

// ---------------- 0: zero degree counters + hg (start-of-call, replay-safe) ----------------
__global__ void zero_kernel(float* __restrict__ hg) {
    int i = blockIdx.x * blockDim.x + threadIdx.x;
    if (i < N_NODES) { g_deg_out[i] = 0; g_deg_in[i] = 0; }
    if (i < N_GRAPHS * HG_LD) hg[i] = 0.f;
}

// ---------------- 1: degree histogram ----------------
__global__ void degree_kernel(const int* __restrict__ src, const int* __restrict__ dst) {
    int i = blockIdx.x * blockDim.x + threadIdx.x;
    if (i < N_EDGES) {
        atomicAdd(&g_deg_out[src[i]], 1);
        atomicAdd(&g_deg_in[dst[i]], 1);
    }
}

// ---------------- 2: per-block partial sums of deg_in ----------------
__global__ void __launch_bounds__(SCAN_BLK)
scan_partial_kernel() {
    __shared__ int wsum[SCAN_BLK / 32];
    int i = blockIdx.x * SCAN_BLK + threadIdx.x;
    int v = (i < N_NODES) ? g_deg_in[i] : 0;
    #pragma unroll
    for (int o = 16; o > 0; o >>= 1) v += __shfl_down_sync(0xFFFFFFFF, v, o);
    int lane = threadIdx.x & 31, wid = threadIdx.x >> 5;
    if (lane == 0) wsum[wid] = v;
    __syncthreads();
    if (wid == 0) {
        int s = (lane < SCAN_BLK / 32) ? wsum[lane] : 0;
        #pragma unroll
        for (int o = 16; o > 0; o >>= 1) s += __shfl_down_sync(0xFFFFFFFF, s, o);
        if (lane == 0) g_blk_off[blockIdx.x] = s;   // raw partial for now
    }
}

// ---------------- 3: scan the 196 partials (one block) ----------------
__global__ void __launch_bounds__(256)
scan_top_kernel() {
    __shared__ int wsum[8];
    int lane = threadIdx.x & 31, wid = threadIdx.x >> 5;
    int v = (threadIdx.x < N_SCAN_BLKS) ? g_blk_off[threadIdx.x] : 0;
    int incl = v;
    #pragma unroll
    for (int o = 1; o < 32; o <<= 1) {
        int t = __shfl_up_sync(0xFFFFFFFF, incl, o);
        if (lane >= o) incl += t;
    }
    if (lane == 31) wsum[wid] = incl;
    __syncthreads();
    if (wid == 0 && lane < 8) {
        int t = wsum[lane];
        int s = t;
        #pragma unroll
        for (int o = 1; o < 8; o <<= 1) {
            int u = __shfl_up_sync(0xFF, s, o);
            if (lane >= o) s += u;
        }
        wsum[lane] = s - t;
    }
    __syncthreads();
    int excl = incl - v + wsum[wid];
    if (threadIdx.x < N_SCAN_BLKS) g_blk_off[threadIdx.x] = excl;
    if (threadIdx.x == N_SCAN_BLKS - 1) {
        g_blk_off[N_SCAN_BLKS] = excl + v;
        g_off[N_NODES] = excl + v;
    }
}

// ---------------- 4: add-back intra-block scan -> off/cursor, plus inv norms ----------------
__global__ void __launch_bounds__(SCAN_BLK)
addback_inv_kernel() {
    __shared__ int wsum[SCAN_BLK / 32];
    int i = blockIdx.x * SCAN_BLK + threadIdx.x;
    int lane = threadIdx.x & 31, wid = threadIdx.x >> 5;
    int v = (i < N_NODES) ? g_deg_in[i] : 0;
    int incl = v;
    #pragma unroll
    for (int o = 1; o < 32; o <<= 1) {
        int t = __shfl_up_sync(0xFFFFFFFF, incl, o);
        if (lane >= o) incl += t;
    }
    if (lane == 31) wsum[wid] = incl;
    __syncthreads();
    if (wid == 0 && lane < SCAN_BLK / 32) {
        int t = wsum[lane];
        int s = t;
        #pragma unroll
        for (int o = 1; o < SCAN_BLK / 32; o <<= 1) {
            int u = __shfl_up_sync(0xFF, s, o);
            if (lane >= o) s += u;
        }
        wsum[lane] = s - t;
    }
    __syncthreads();
    if (i < N_NODES) {
        int off = g_blk_off[blockIdx.x] + incl - v + wsum[wid];
        g_off[i]    = off;
        g_cursor[i] = off;
        g_out_inv[i] = rsqrtf(fmaxf((float)g_deg_out[i], 1.0f));
        g_in_inv[i]  = rsqrtf(fmaxf((float)v, 1.0f));
    }
}

// ---------------- 5: bucket fill ----------------
__global__ void fill_kernel(const int* __restrict__ src, const int* __restrict__ dst) {
    int e = blockIdx.x * blockDim.x + threadIdx.x;
    if (e < N_EDGES) {
        int s = src[e];
        int d = dst[e];
        int pos = atomicAdd(&g_cursor[d], 1);
        g_edges[pos] = make_int2(s, __float_as_int(g_out_inv[s]));
    }
}

// ---------------- fused per-layer kernel: gather -> smem -> GEMM -> PReLU -> pool ----------------
// X and Hout MUST be disjoint buffers (gather reads arbitrary X rows while epilogue writes Hout).
#define TM 64
#define XLD 132   // padded x-tile stride

__global__ void __launch_bounds__(256)
fused_layer_kernel(const float* __restrict__ X,
                   const float* __restrict__ W,
                   const float* __restrict__ a_ptr,
                   const int* __restrict__ graph_id,
                   float* __restrict__ Hout,
                   float* __restrict__ hg,
                   int hg_col_off) {
    extern __shared__ float sm[];
    float* Ws = sm;              // D*D floats (64 KB)
    float* Xs = sm + D * D;      // TM*XLD floats (~33.8 KB)

    int tid  = threadIdx.x;
    int lane = tid & 31;
    int wid  = tid >> 5;
    int row0 = blockIdx.x * TM;

    // stage W (row-major [k][c]) — protected by the post-gather __syncthreads
    {
        float4* Ws4 = reinterpret_cast<float4*>(Ws);
        const float4* W4 = reinterpret_cast<const float4*>(W);
        for (int i = tid; i < D * D / 4; i += 256) Ws4[i] = W4[i];
    }

    // gather phase: warp w handles rows w, w+8, ..., w+56; lane owns float4 cols
    {
        const float4* X4 = reinterpret_cast<const float4*>(X);
        for (int r = wid; r < TM; r += 8) {
            int node = row0 + r;
            float4 acc = make_float4(0.f, 0.f, 0.f, 0.f);
            if (node < N_NODES) {
                int beg = g_off[node];
                int end = g_off[node + 1];
                int j = beg;
                for (; j + 4 <= end; j += 4) {
                    int2 e0 = g_edges[j + 0];
                    int2 e1 = g_edges[j + 1];
                    int2 e2 = g_edges[j + 2];
                    int2 e3 = g_edges[j + 3];
                    float4 v0 = X4[e0.x * (D / 4) + lane];
                    float4 v1 = X4[e1.x * (D / 4) + lane];
                    float4 v2 = X4[e2.x * (D / 4) + lane];
                    float4 v3 = X4[e3.x * (D / 4) + lane];
                    float w0 = __int_as_float(e0.y);
                    float w1 = __int_as_float(e1.y);
                    float w2 = __int_as_float(e2.y);
                    float w3 = __int_as_float(e3.y);
                    acc.x += v0.x * w0; acc.y += v0.y * w0; acc.z += v0.z * w0; acc.w += v0.w * w0;
                    acc.x += v1.x * w1; acc.y += v1.y * w1; acc.z += v1.z * w1; acc.w += v1.w * w1;
                    acc.x += v2.x * w2; acc.y += v2.y * w2; acc.z += v2.z * w2; acc.w += v2.w * w2;
                    acc.x += v3.x * w3; acc.y += v3.y * w3; acc.z += v3.z * w3; acc.w += v3.w * w3;
                }
                for (; j < end; j++) {
                    int2 e = g_edges[j];
                    float4 v = X4[e.x * (D / 4) + lane];
                    float w = __int_as_float(e.y);
                    acc.x += v.x * w; acc.y += v.y * w; acc.z += v.z * w; acc.w += v.w * w;
                }
                float s = g_in_inv[node];
                acc.x *= s; acc.y *= s; acc.z *= s; acc.w *= s;
            }
            *reinterpret_cast<float4*>(&Xs[r * XLD + lane * 4]) = acc;
        }
    }
    __syncthreads();

    // GEMM phase
    int rg = tid >> 4;   // 0..15 -> rows rg*4 .. rg*4+3
    int cg = tid & 15;   // 0..15 -> cols cg*8 .. cg*8+7

    unsigned long long acc2[4][4];
    #pragma unroll
    for (int i = 0; i < 4; i++)
        #pragma unroll
        for (int p = 0; p < 4; p++) acc2[i][p] = 0ull;

    #pragma unroll 2
    for (int k4 = 0; k4 < D / 4; k4++) {
        float xr[4][4];
        #pragma unroll
        for (int i = 0; i < 4; i++) {
            float4 t = *reinterpret_cast<const float4*>(&Xs[(rg * 4 + i) * XLD + k4 * 4]);
            xr[i][0] = t.x; xr[i][1] = t.y; xr[i][2] = t.z; xr[i][3] = t.w;
        }
        #pragma unroll
        for (int kk = 0; kk < 4; kk++) {
            int k = k4 * 4 + kk;
            const ulonglong2* wp =
                reinterpret_cast<const ulonglong2*>(&Ws[k * D + cg * 8]);
            ulonglong2 wa = wp[0];
            ulonglong2 wb = wp[1];
            #pragma unroll
            for (int i = 0; i < 4; i++) {
                unsigned long long x2 = bc2(xr[i][kk]);
                ffma2(acc2[i][0], x2, wa.x);
                ffma2(acc2[i][1], x2, wa.y);
                ffma2(acc2[i][2], x2, wb.x);
                ffma2(acc2[i][3], x2, wb.y);
            }
        }
    }

    float alpha = __ldg(a_ptr);
    int colbase = cg * 8;

    int   grow[4];
    bool  valid[4];
    #pragma unroll
    for (int i = 0; i < 4; i++) {
        int row = row0 + rg * 4 + i;
        valid[i] = (row < N_NODES);
        grow[i]  = valid[i] ? __ldg(&graph_id[row]) : -1;
    }

    float hv[4][8];
    #pragma unroll
    for (int i = 0; i < 4; i++) {
        #pragma unroll
        for (int p = 0; p < 4; p++) {
            float2 v = unpk2(acc2[i][p]);
            hv[i][2 * p]     = v.x > 0.f ? v.x : alpha * v.x;
            hv[i][2 * p + 1] = v.y > 0.f ? v.y : alpha * v.y;
        }
        if (valid[i]) {
            int row = row0 + rg * 4 + i;
            float4 s0 = make_float4(hv[i][0], hv[i][1], hv[i][2], hv[i][3]);
            float4 s1 = make_float4(hv[i][4], hv[i][5], hv[i][6], hv[i][7]);
            *reinterpret_cast<float4*>(&Hout[row * D + colbase])     = s0;
            *reinterpret_cast<float4*>(&Hout[row * D + colbase + 4]) = s1;
        }
    }

    bool same = valid[0] & valid[3] & (grow[0] == grow[1]) & (grow[1] == grow[2]) & (grow[2] == grow[3]);
    if (same) {
        float* base = &hg[grow[0] * HG_LD + hg_col_off + colbase];
        #pragma unroll
        for (int j = 0; j < 8; j++) {
            float s = hv[0][j] + hv[1][j] + hv[2][j] + hv[3][j];
            atomicAdd(base + j, s);
        }
    } else {
        #pragma unroll
        for (int i = 0; i < 4; i++) {
            if (!valid[i]) continue;
            float* base = &hg[grow[i] * HG_LD + hg_col_off + colbase];
            #pragma unroll
            for (int j = 0; j < 8; j++) atomicAdd(base + j, hv[i][j]);
        }
    }
}

// ---------------- launch ----------------
extern "C" void kernel_launch(void* const* d_in, const int* in_sizes, int n_in,
                              void* d_out, int out_size) {
    const float* feat = (const float*)d_in[0];
    const float* W0   = (const float*)d_in[1];
    const float* W1   = (const float*)d_in[2];
    const float* W2   = (const float*)d_in[3];
    const float* a0   = (const float*)d_in[4];
    const float* a1   = (const float*)d_in[5];
    const float* a2   = (const float*)d_in[6];
    const int*   src  = (const int*)d_in[7];
    const int*   dst  = (const int*)d_in[8];
    const int*   gid  = (const int*)d_in[9];

    float* out_h  = (float*)d_out;                 // [N_NODES, D]
    float* out_hg = (float*)d_out + N_NODES * D;   // [N_GRAPHS, 3*D]

    void* h1_sym = nullptr; cudaGetSymbolAddress(&h1_sym, g_h);
    void* h2_sym = nullptr; cudaGetSymbolAddress(&h2_sym, g_h2);
    float* h1 = (float*)h1_sym;
    float* h2 = (float*)h2_sym;

    const int smem_bytes = (D * D + TM * XLD) * sizeof(float);
    static bool attr_set = false;
    if (!attr_set) {
        cudaFuncSetAttribute(fused_layer_kernel,
                             cudaFuncAttributeMaxDynamicSharedMemorySize, smem_bytes);
        attr_set = true;
    }

    // ---- build CSR (by dst) + norms: 6 launches ----
    {
        int nz = N_GRAPHS * HG_LD;   // 192000 covers both hg and node arrays
        zero_kernel<<<(nz + 255) / 256, 256>>>(out_hg);                  // #1
    }
    degree_kernel<<<(N_EDGES + 255) / 256, 256>>>(src, dst);             // #2
    scan_partial_kernel<<<N_SCAN_BLKS, SCAN_BLK>>>();                    // #3
    scan_top_kernel<<<1, 256>>>();                                       // #4
    addback_inv_kernel<<<N_SCAN_BLKS, SCAN_BLK>>>();                     // #5
    fill_kernel<<<(N_EDGES + 255) / 256, 256>>>(src, dst);               // #6

    int blocks = (N_NODES + TM - 1) / TM;

    // layer 0: feat -> h1 ; layer 1: h1 -> h2 ; layer 2: h2 -> out_h
    fused_layer_kernel<<<blocks, 256, smem_bytes>>>(                     // #7
        feat, W0, a0, gid, h1, out_hg, 0 * D);
    fused_layer_kernel<<<blocks, 256, smem_bytes>>>(                     // #8
        h1, W1, a1, gid, h2, out_hg, 1 * D);
    fused_layer_kernel<<<blocks, 256, smem_bytes>>>(                     // #9
        h2, W2, a2, gid, out_h, out_hg, 2 * D);
}

// round 10
// speedup vs baseline: 1.1784x; 1.1784x over previous
#include <cuda_runtime.h>
#include <cuda_fp16.h>
#include <math.h>

#define N_NODES  50000
#define N_GRAPHS 500
#define N_EDGES  800000
#define D        128
#define HG_LD    (3 * D)   // 384

#define SCAN_BLK 256
#define N_SCAN_BLKS ((N_NODES + SCAN_BLK - 1) / SCAN_BLK)   // 196

// ---------------- scratch (no allocs) ----------------
__device__ __half g_xh[N_NODES * D];        // fp16 gather operand, pre-scaled by out_inv
__device__ float  g_agg[N_NODES * D];       // fp32 aggregation (includes in_inv)
__device__ float  g_out_inv[N_NODES];
__device__ float  g_in_inv[N_NODES];
__device__ int    g_deg_out[N_NODES];
__device__ int    g_deg_in[N_NODES];
__device__ int    g_off[N_NODES + 1];       // CSR offsets by dst
__device__ int    g_cursor[N_NODES];        // fill cursors
__device__ int    g_blk_off[N_SCAN_BLKS + 1];
__device__ int    g_edge_src[N_EDGES];      // src only (weight folded into g_xh)

// ---------------- packed f32x2 helpers ----------------
__device__ __forceinline__ void ffma2(unsigned long long& acc,
                                      unsigned long long x,
                                      unsigned long long w) {
    asm("fma.rn.f32x2 %0, %1, %2, %0;" : "+l"(acc) : "l"(x), "l"(w));
}
__device__ __forceinline__ unsigned long long bc2(float x) {
    unsigned long long r;
    asm("mov.b64 %0, {%1, %1};" : "=l"(r) : "f"(x));
    return r;
}
__device__ __forceinline__ float2 unpk2(unsigned long long v) {
    float2 r;
    asm("mov.b64 {%0, %1}, %2;" : "=f"(r.x), "=f"(r.y) : "l"(v));
    return r;
}

// ---------------- 0: zero degree counters + hg (start-of-call, replay-safe) ----------------
__global__ void zero_kernel(float* __restrict__ hg) {
    int i = blockIdx.x * blockDim.x + threadIdx.x;
    if (i < N_NODES) { g_deg_out[i] = 0; g_deg_in[i] = 0; }
    if (i < N_GRAPHS * HG_LD) hg[i] = 0.f;
}

// ---------------- 1: degree histogram ----------------
__global__ void degree_kernel(const int* __restrict__ src, const int* __restrict__ dst) {
    int i = blockIdx.x * blockDim.x + threadIdx.x;
    if (i < N_EDGES) {
        atomicAdd(&g_deg_out[src[i]], 1);
        atomicAdd(&g_deg_in[dst[i]], 1);
    }
}

// ---------------- 2: per-block partial sums of deg_in ----------------
__global__ void __launch_bounds__(SCAN_BLK)
scan_partial_kernel() {
    __shared__ int wsum[SCAN_BLK / 32];
    int i = blockIdx.x * SCAN_BLK + threadIdx.x;
    int v = (i < N_NODES) ? g_deg_in[i] : 0;
    #pragma unroll
    for (int o = 16; o > 0; o >>= 1) v += __shfl_down_sync(0xFFFFFFFF, v, o);
    int lane = threadIdx.x & 31, wid = threadIdx.x >> 5;
    if (lane == 0) wsum[wid] = v;
    __syncthreads();
    if (wid == 0) {
        int s = (lane < SCAN_BLK / 32) ? wsum[lane] : 0;
        #pragma unroll
        for (int o = 16; o > 0; o >>= 1) s += __shfl_down_sync(0xFFFFFFFF, s, o);
        if (lane == 0) g_blk_off[blockIdx.x] = s;
    }
}

// ---------------- 3: scan the 196 partials (one block) ----------------
__global__ void __launch_bounds__(256)
scan_top_kernel() {
    __shared__ int wsum[8];
    int lane = threadIdx.x & 31, wid = threadIdx.x >> 5;
    int v = (threadIdx.x < N_SCAN_BLKS) ? g_blk_off[threadIdx.x] : 0;
    int incl = v;
    #pragma unroll
    for (int o = 1; o < 32; o <<= 1) {
        int t = __shfl_up_sync(0xFFFFFFFF, incl, o);
        if (lane >= o) incl += t;
    }
    if (lane == 31) wsum[wid] = incl;
    __syncthreads();
    if (wid == 0 && lane < 8) {
        int t = wsum[lane];
        int s = t;
        #pragma unroll
        for (int o = 1; o < 8; o <<= 1) {
            int u = __shfl_up_sync(0xFF, s, o);
            if (lane >= o) s += u;
        }
        wsum[lane] = s - t;
    }
    __syncthreads();
    int excl = incl - v + wsum[wid];
    if (threadIdx.x < N_SCAN_BLKS) g_blk_off[threadIdx.x] = excl;
    if (threadIdx.x == N_SCAN_BLKS - 1) {
        g_blk_off[N_SCAN_BLKS] = excl + v;
        g_off[N_NODES] = excl + v;
    }
}

// ---------------- 4: add-back intra-block scan -> off/cursor, plus inv norms ----------------
__global__ void __launch_bounds__(SCAN_BLK)
addback_inv_kernel() {
    __shared__ int wsum[SCAN_BLK / 32];
    int i = blockIdx.x * SCAN_BLK + threadIdx.x;
    int lane = threadIdx.x & 31, wid = threadIdx.x >> 5;
    int v = (i < N_NODES) ? g_deg_in[i] : 0;
    int incl = v;
    #pragma unroll
    for (int o = 1; o < 32; o <<= 1) {
        int t = __shfl_up_sync(0xFFFFFFFF, incl, o);
        if (lane >= o) incl += t;
    }
    if (lane == 31) wsum[wid] = incl;
    __syncthreads();
    if (wid == 0 && lane < SCAN_BLK / 32) {
        int t = wsum[lane];
        int s = t;
        #pragma unroll
        for (int o = 1; o < SCAN_BLK / 32; o <<= 1) {
            int u = __shfl_up_sync(0xFF, s, o);
            if (lane >= o) s += u;
        }
        wsum[lane] = s - t;
    }
    __syncthreads();
    if (i < N_NODES) {
        int off = g_blk_off[blockIdx.x] + incl - v + wsum[wid];
        g_off[i]    = off;
        g_cursor[i] = off;
        g_out_inv[i] = rsqrtf(fmaxf((float)g_deg_out[i], 1.0f));
        g_in_inv[i]  = rsqrtf(fmaxf((float)v, 1.0f));
    }
}

// ---------------- 5: bucket fill (src only; weight folded into Xh) ----------------
__global__ void fill_kernel(const int* __restrict__ src, const int* __restrict__ dst) {
    int e = blockIdx.x * blockDim.x + threadIdx.x;
    if (e < N_EDGES) {
        int d = dst[e];
        int pos = atomicAdd(&g_cursor[d], 1);
        g_edge_src[pos] = src[e];
    }
}

// ---------------- 6: feat * out_inv -> fp16 Xh ----------------
__global__ void convert_kernel(const float* __restrict__ feat) {
    int i = blockIdx.x * blockDim.x + threadIdx.x;     // one per 4 elems
    if (i < N_NODES * D / 4) {
        int row = i >> 5;   // D/4 = 32 per row
        float w = g_out_inv[row];
        float4 v = reinterpret_cast<const float4*>(feat)[i];
        __half2 h0 = __floats2half2_rn(v.x * w, v.y * w);
        __half2 h1 = __floats2half2_rn(v.z * w, v.w * w);
        uint2 pk;
        pk.x = *reinterpret_cast<unsigned int*>(&h0);
        pk.y = *reinterpret_cast<unsigned int*>(&h1);
        reinterpret_cast<uint2*>(g_xh)[i] = pk;
    }
}

// ---------------- gather: agg[n] = in_inv[n] * sum Xh[src]  (fp16 rows, fp32 acc) ----------------
// One warp per node; lane owns 4 cols (uint2 = 4 halves = 8 B; 32 lanes = 256 B row).
__global__ void __launch_bounds__(256)
gather_kernel() {
    int gtid = blockIdx.x * blockDim.x + threadIdx.x;
    int node = gtid >> 5;
    int lane = gtid & 31;
    if (node >= N_NODES) return;
    int beg = g_off[node];
    int end = g_off[node + 1];

    const uint2* X2 = reinterpret_cast<const uint2*>(g_xh);
    float4 acc = make_float4(0.f, 0.f, 0.f, 0.f);

    int j = beg;
    for (; j + 4 <= end; j += 4) {
        int s0 = g_edge_src[j + 0];
        int s1 = g_edge_src[j + 1];
        int s2 = g_edge_src[j + 2];
        int s3 = g_edge_src[j + 3];
        uint2 v0 = X2[s0 * 32 + lane];
        uint2 v1 = X2[s1 * 32 + lane];
        uint2 v2 = X2[s2 * 32 + lane];
        uint2 v3 = X2[s3 * 32 + lane];
        #define ACC4(v) { \
            float2 a = __half22float2(*reinterpret_cast<__half2*>(&(v).x)); \
            float2 b = __half22float2(*reinterpret_cast<__half2*>(&(v).y)); \
            acc.x += a.x; acc.y += a.y; acc.z += b.x; acc.w += b.y; }
        ACC4(v0) ACC4(v1) ACC4(v2) ACC4(v3)
    }
    for (; j < end; j++) {
        int s = g_edge_src[j];
        uint2 v = X2[s * 32 + lane];
        ACC4(v)
        #undef ACC4
    }

    float s = g_in_inv[node];
    acc.x *= s; acc.y *= s; acc.z *= s; acc.w *= s;
    reinterpret_cast<float4*>(g_agg)[node * 32 + lane] = acc;
}

// ---------------- GEMM + PReLU + pool; writes next-layer Xh (fp16) or final h (fp32) ----------------
#define TM 64
#define XLD 132   // padded x-tile stride

__global__ void __launch_bounds__(256)
gemm_prelu_pool_kernel(const float* __restrict__ W,
                       const float* __restrict__ a_ptr,
                       const int* __restrict__ graph_id,
                       float* __restrict__ Hout_f32,   // used when last_layer
                       float* __restrict__ hg,
                       int hg_col_off,
                       int last_layer) {
    extern __shared__ float sm[];
    float* Ws = sm;              // D*D floats (64 KB)
    float* Xs = sm + D * D;      // TM*XLD floats

    int tid  = threadIdx.x;
    int row0 = blockIdx.x * TM;

    // stage W
    {
        float4* Ws4 = reinterpret_cast<float4*>(Ws);
        const float4* W4 = reinterpret_cast<const float4*>(W);
        for (int i = tid; i < D * D / 4; i += 256) Ws4[i] = W4[i];
    }
    // stage X tile from g_agg
    {
        const float4* X4 = reinterpret_cast<const float4*>(g_agg);
        for (int i = tid; i < TM * (D / 4); i += 256) {
            int r  = i >> 5;
            int k4 = i & 31;
            int row = row0 + r;
            float4 v = make_float4(0.f, 0.f, 0.f, 0.f);
            if (row < N_NODES) v = X4[row * 32 + k4];
            *reinterpret_cast<float4*>(&Xs[r * XLD + k4 * 4]) = v;
        }
    }
    __syncthreads();

    int rg = tid >> 4;
    int cg = tid & 15;

    unsigned long long acc2[4][4];
    #pragma unroll
    for (int i = 0; i < 4; i++)
        #pragma unroll
        for (int p = 0; p < 4; p++) acc2[i][p] = 0ull;

    #pragma unroll 2
    for (int k4 = 0; k4 < D / 4; k4++) {
        float xr[4][4];
        #pragma unroll
        for (int i = 0; i < 4; i++) {
            float4 t = *reinterpret_cast<const float4*>(&Xs[(rg * 4 + i) * XLD + k4 * 4]);
            xr[i][0] = t.x; xr[i][1] = t.y; xr[i][2] = t.z; xr[i][3] = t.w;
        }
        #pragma unroll
        for (int kk = 0; kk < 4; kk++) {
            int k = k4 * 4 + kk;
            const ulonglong2* wp =
                reinterpret_cast<const ulonglong2*>(&Ws[k * D + cg * 8]);
            ulonglong2 wa = wp[0];
            ulonglong2 wb = wp[1];
            #pragma unroll
            for (int i = 0; i < 4; i++) {
                unsigned long long x2 = bc2(xr[i][kk]);
                ffma2(acc2[i][0], x2, wa.x);
                ffma2(acc2[i][1], x2, wa.y);
                ffma2(acc2[i][2], x2, wb.x);
                ffma2(acc2[i][3], x2, wb.y);
            }
        }
    }

    float alpha = __ldg(a_ptr);
    int colbase = cg * 8;

    int   grow[4];
    bool  valid[4];
    #pragma unroll
    for (int i = 0; i < 4; i++) {
        int row = row0 + rg * 4 + i;
        valid[i] = (row < N_NODES);
        grow[i]  = valid[i] ? __ldg(&graph_id[row]) : -1;
    }

    float hv[4][8];
    #pragma unroll
    for (int i = 0; i < 4; i++) {
        #pragma unroll
        for (int p = 0; p < 4; p++) {
            float2 v = unpk2(acc2[i][p]);
            hv[i][2 * p]     = v.x > 0.f ? v.x : alpha * v.x;
            hv[i][2 * p + 1] = v.y > 0.f ? v.y : alpha * v.y;
        }
        if (valid[i]) {
            int row = row0 + rg * 4 + i;
            if (last_layer) {
                float4 s0 = make_float4(hv[i][0], hv[i][1], hv[i][2], hv[i][3]);
                float4 s1 = make_float4(hv[i][4], hv[i][5], hv[i][6], hv[i][7]);
                *reinterpret_cast<float4*>(&Hout_f32[row * D + colbase])     = s0;
                *reinterpret_cast<float4*>(&Hout_f32[row * D + colbase + 4]) = s1;
            } else {
                float w = g_out_inv[row];
                __half2 p0 = __floats2half2_rn(hv[i][0] * w, hv[i][1] * w);
                __half2 p1 = __floats2half2_rn(hv[i][2] * w, hv[i][3] * w);
                __half2 p2 = __floats2half2_rn(hv[i][4] * w, hv[i][5] * w);
                __half2 p3 = __floats2half2_rn(hv[i][6] * w, hv[i][7] * w);
                uint4 pk;
                pk.x = *reinterpret_cast<unsigned int*>(&p0);
                pk.y = *reinterpret_cast<unsigned int*>(&p1);
                pk.z = *reinterpret_cast<unsigned int*>(&p2);
                pk.w = *reinterpret_cast<unsigned int*>(&p3);
                *reinterpret_cast<uint4*>(&g_xh[row * D + colbase]) = pk;
            }
        }
    }

    bool same = valid[0] & valid[3] & (grow[0] == grow[1]) & (grow[1] == grow[2]) & (grow[2] == grow[3]);
    if (same) {
        float* base = &hg[grow[0] * HG_LD + hg_col_off + colbase];
        #pragma unroll
        for (int j = 0; j < 8; j++) {
            float s = hv[0][j] + hv[1][j] + hv[2][j] + hv[3][j];
            atomicAdd(base + j, s);
        }
    } else {
        #pragma unroll
        for (int i = 0; i < 4; i++) {
            if (!valid[i]) continue;
            float* base = &hg[grow[i] * HG_LD + hg_col_off + colbase];
            #pragma unroll
            for (int j = 0; j < 8; j++) atomicAdd(base + j, hv[i][j]);
        }
    }
}

// ---------------- launch ----------------
extern "C" void kernel_launch(void* const* d_in, const int* in_sizes, int n_in,
                              void* d_out, int out_size) {
    const float* feat = (const float*)d_in[0];
    const float* W0   = (const float*)d_in[1];
    const float* W1   = (const float*)d_in[2];
    const float* W2   = (const float*)d_in[3];
    const float* a0   = (const float*)d_in[4];
    const float* a1   = (const float*)d_in[5];
    const float* a2   = (const float*)d_in[6];
    const int*   src  = (const int*)d_in[7];
    const int*   dst  = (const int*)d_in[8];
    const int*   gid  = (const int*)d_in[9];

    float* out_h  = (float*)d_out;                 // [N_NODES, D]
    float* out_hg = (float*)d_out + N_NODES * D;   // [N_GRAPHS, 3*D]

    const int smem_bytes = (D * D + TM * XLD) * sizeof(float);
    static bool attr_set = false;
    if (!attr_set) {
        cudaFuncSetAttribute(gemm_prelu_pool_kernel,
                             cudaFuncAttributeMaxDynamicSharedMemorySize, smem_bytes);
        attr_set = true;
    }

    // ---- build: CSR (by dst) + norms + fp16 operand ----
    {
        int nz = N_GRAPHS * HG_LD;
        zero_kernel<<<(nz + 255) / 256, 256>>>(out_hg);
    }
    degree_kernel<<<(N_EDGES + 255) / 256, 256>>>(src, dst);
    scan_partial_kernel<<<N_SCAN_BLKS, SCAN_BLK>>>();
    scan_top_kernel<<<1, 256>>>();
    addback_inv_kernel<<<N_SCAN_BLKS, SCAN_BLK>>>();
    fill_kernel<<<(N_EDGES + 255) / 256, 256>>>(src, dst);
    convert_kernel<<<(N_NODES * D / 4 + 255) / 256, 256>>>(feat);

    const float* Ws[3] = {W0, W1, W2};
    const float* as[3] = {a0, a1, a2};

    int gather_blocks = (N_NODES * 32 + 255) / 256;
    int gemm_blocks   = (N_NODES + TM - 1) / TM;

    for (int l = 0; l < 3; l++) {
        gather_kernel<<<gather_blocks, 256>>>();
        gemm_prelu_pool_kernel<<<gemm_blocks, 256, smem_bytes>>>(
            Ws[l], as[l], gid, out_h, out_hg, l * D, (l == 2) ? 1 : 0);
    }
}